// round 9
// baseline (speedup 1.0000x reference)
#include <cuda_runtime.h>
#include <cuda_bf16.h>
#include <stdint.h>

#define NSM 148
#define ST1 49152
#define ST2 65536
#define SMEM1 (1024 + 3 * ST1)
#define SMEM2 (1024 + 3 * ST2)

static __device__ uint32_t g_scr[(size_t)8 * 1024 * 4096];   // packed bf16 hi/lo inter
static __device__ uint4 Xq1[(size_t)8192 * 128];             // int8 slice1 of X
static __device__ uint4 Xq2[(size_t)8192 * 128];
static __device__ uint4 Wq1[(size_t)65536 * 128];            // int8 Wgu^T [e][n][k]
static __device__ uint4 Wq2[(size_t)65536 * 128];
static __device__ float sX_d[8192];
static __device__ float sW_d[65536];

__device__ __forceinline__ uint32_t s2u(const void* p) {
    uint32_t a;
    asm("{ .reg .u64 t; cvta.to.shared.u64 t, %1; cvt.u32.u64 %0, t; }" : "=r"(a) : "l"(p));
    return a;
}
__device__ __forceinline__ uint32_t swzA(uint32_t o) { return o ^ ((o >> 3) & 0x70); }
__device__ __forceinline__ uint32_t swzB(uint32_t o) { return o ^ ((o >> 4) & 0x70); }
__device__ __forceinline__ uint32_t pk(float a, float b) {
    __nv_bfloat162 h = __floats2bfloat162_rn(a, b);
    return *reinterpret_cast<uint32_t*>(&h);
}
__device__ __forceinline__ void split2(float f0, float f1, uint32_t& hi, uint32_t& lo) {
    const uint32_t u0 = __float_as_uint(f0), u1 = __float_as_uint(f1);
    asm("prmt.b32 %0, %1, %2, 0x7632;" : "=r"(hi) : "r"(u0), "r"(u1));
    lo = pk(f0 - __uint_as_float(u0 & 0xFFFF0000u), f1 - __uint_as_float(u1 & 0xFFFF0000u));
}
__device__ __forceinline__ uint32_t pack_hl(float f) {
    __nv_bfloat16 hb = __float2bfloat16(f);
    __nv_bfloat16 lb = __float2bfloat16(f - __bfloat162float(hb));
    return ((uint32_t)__bfloat16_as_ushort(hb) << 16) | (uint32_t)__bfloat16_as_ushort(lb);
}
__device__ __forceinline__ float silu_mul(float g, float u) {
    return u * __fdividef(g, 1.0f + __expf(-g));
}
__device__ __forceinline__ uint32_t pack4i8(int a, int b, int c, int d) {
    return (uint32_t)(a & 255) | ((uint32_t)(b & 255) << 8) |
           ((uint32_t)(c & 255) << 16) | ((uint32_t)(d & 255) << 24);
}
__device__ __forceinline__ void ldsm4(uint32_t* r, uint32_t addr) {
    asm volatile("ldmatrix.sync.aligned.m8n8.x4.shared.b16 {%0,%1,%2,%3}, [%4];"
                 : "=r"(r[0]), "=r"(r[1]), "=r"(r[2]), "=r"(r[3]) : "r"(addr));
}
__device__ __forceinline__ void ldsm4t(uint32_t* r, uint32_t addr) {
    asm volatile("ldmatrix.sync.aligned.m8n8.x4.trans.shared.b16 {%0,%1,%2,%3}, [%4];"
                 : "=r"(r[0]), "=r"(r[1]), "=r"(r[2]), "=r"(r[3]) : "r"(addr));
}
__device__ __forceinline__ void mma16816(float* c, const uint32_t* a, const uint32_t* b) {
    asm volatile(
        "mma.sync.aligned.m16n8k16.row.col.f32.bf16.bf16.f32 "
        "{%0,%1,%2,%3}, {%4,%5,%6,%7}, {%8,%9}, {%0,%1,%2,%3};"
        : "+f"(c[0]), "+f"(c[1]), "+f"(c[2]), "+f"(c[3])
        : "r"(a[0]), "r"(a[1]), "r"(a[2]), "r"(a[3]), "r"(b[0]), "r"(b[1]));
}
__device__ __forceinline__ void imma(int* c, const uint32_t* a, uint32_t b0, uint32_t b1) {
    asm volatile(
        "mma.sync.aligned.m16n8k32.row.col.s32.s8.s8.s32 "
        "{%0,%1,%2,%3}, {%4,%5,%6,%7}, {%8,%9}, {%0,%1,%2,%3};"
        : "+r"(c[0]), "+r"(c[1]), "+r"(c[2]), "+r"(c[3])
        : "r"(a[0]), "r"(a[1]), "r"(a[2]), "r"(a[3]), "r"(b0), "r"(b1));
}

#define MBAR_INIT(addr, cnt) \
    asm volatile("mbarrier.init.shared.b64 [%0], %1;" :: "r"(addr), "r"((uint32_t)(cnt)) : "memory")
#define MBAR_ARRIVE(addr) \
    asm volatile("mbarrier.arrive.shared.b64 _, [%0];" :: "r"(addr) : "memory")
#define MBAR_WAIT(mbar_addr, phase_parity) do {                                            \
    uint32_t _mbar = (uint32_t)(mbar_addr);                                                \
    uint32_t _par  = (uint32_t)(phase_parity);                                             \
    uint32_t _done;                                                                        \
    asm volatile(                                                                          \
        "{\n\t.reg .pred p;\n\t"                                                           \
        "mbarrier.try_wait.parity.acquire.cta.shared::cta.b64 p, [%1], %2;\n\t"            \
        "selp.b32 %0, 1, 0, p;\n\t}"                                                       \
        : "=r"(_done) : "r"(_mbar), "r"(_par) : "memory");                                 \
    if (!_done) {                                                                          \
        asm volatile(                                                                      \
            "{\n\t.reg .pred P1;\n\t"                                                      \
            "WL_%=:\n\t"                                                                   \
            "mbarrier.try_wait.parity.acquire.cta.shared::cta.b64 P1, [%0], %1, 0x989680;\n\t" \
            "@P1 bra.uni WD_%=;\n\t"                                                       \
            "bra.uni WL_%=;\n\t"                                                           \
            "WD_%=:\n\t}"                                                                  \
            :: "r"(_mbar), "r"(_par) : "memory");                                          \
    }                                                                                      \
} while (0)

// ===================== prepass: quantize X per-row, 2 slices =================
__global__ __launch_bounds__(256) void quantX_ker(const float* __restrict__ X) {
    __shared__ float red[8];
    const int row = blockIdx.x, t = threadIdx.x;
    const float4* xr = reinterpret_cast<const float4*>(X + (size_t)row * 2048);
    float4 v0 = __ldg(xr + t * 2), v1 = __ldg(xr + t * 2 + 1);
    float m = fmaxf(fmaxf(fabsf(v0.x), fabsf(v0.y)), fmaxf(fabsf(v0.z), fabsf(v0.w)));
    m = fmaxf(m, fmaxf(fmaxf(fabsf(v1.x), fabsf(v1.y)), fmaxf(fabsf(v1.z), fabsf(v1.w))));
    #pragma unroll
    for (int o = 16; o; o >>= 1) m = fmaxf(m, __shfl_xor_sync(~0u, m, o));
    if ((t & 31) == 0) red[t >> 5] = m;
    __syncthreads();
    m = 1e-30f;
    #pragma unroll
    for (int i = 0; i < 8; i++) m = fmaxf(m, red[i]);
    if (t == 0) sX_d[row] = m;
    const float inv = 127.0f / m;
    const float* vv[2] = {&v0.x, &v1.x};
    uint32_t o1[2], o2[2];
    #pragma unroll
    for (int i = 0; i < 2; i++) {
        int q1[4], q2[4];
        #pragma unroll
        for (int j = 0; j < 4; j++) {
            float q = vv[i][j] * inv, f1 = rintf(q);
            q1[j] = (int)f1;
            q2[j] = __float2int_rn((q - f1) * 254.0f);
        }
        o1[i] = pack4i8(q1[0], q1[1], q1[2], q1[3]);
        o2[i] = pack4i8(q2[0], q2[1], q2[2], q2[3]);
    }
    reinterpret_cast<uint2*>(Xq1)[(size_t)row * 256 + t] = make_uint2(o1[0], o1[1]);
    reinterpret_cast<uint2*>(Xq2)[(size_t)row * 256 + t] = make_uint2(o2[0], o2[1]);
}

// ============ prepass: quantize Wgu per-col, transpose to [e][n][k] ==========
__global__ __launch_bounds__(128) void quantW_ker(const float* __restrict__ W) {
    const int e = blockIdx.x >> 6;
    const int col = (blockIdx.x & 63) * 128 + threadIdx.x;
    const float* p = W + (size_t)e * 2048 * 8192 + col;
    float m = 1e-30f;
    for (int k = 0; k < 2048; k += 8) {
        #pragma unroll
        for (int j = 0; j < 8; j++) m = fmaxf(m, fabsf(__ldg(p + (size_t)(k + j) * 8192)));
    }
    sW_d[e * 8192 + col] = m;
    const float inv = 127.0f / m;
    const size_t ob = ((size_t)e * 8192 + col) * 128;
    for (int k0 = 0; k0 < 2048; k0 += 16) {
        uint32_t u1[4], u2[4];
        #pragma unroll
        for (int q = 0; q < 4; q++) {
            int q1[4], q2[4];
            #pragma unroll
            for (int b = 0; b < 4; b++) {
                float x = __ldg(p + (size_t)(k0 + q * 4 + b) * 8192) * inv;
                float f1 = rintf(x);
                q1[b] = (int)f1;
                q2[b] = __float2int_rn((x - f1) * 254.0f);
            }
            u1[q] = pack4i8(q1[0], q1[1], q1[2], q1[3]);
            u2[q] = pack4i8(q2[0], q2[1], q2[2], q2[3]);
        }
        Wq1[ob + k0 / 16] = make_uint4(u1[0], u1[1], u1[2], u1[3]);
        Wq2[ob + k0 / 16] = make_uint4(u2[0], u2[1], u2[2], u2[3]);
    }
}

// ============ GEMM1 (int8 2-slice): SwiGLU -> g_scr. CTA 128m x 64n ==========
// Persistent. 384 thr = 8 consumers (4m x 2n, 32x32) + 4 producers. Kc=128.
// Stage: A1@0(16K), A2@16K, B1@32K(8K), B2@40K.
__global__ __launch_bounds__(384, 1) void gemm1_ker() {
    extern __shared__ char smem[];
    const int tid = threadIdx.x, wid = tid >> 5, lane = tid & 31;
    const uint32_t smbase = s2u(smem), tiles_u = (smbase + 1023) & ~1023u;
    char* tiles = smem + (tiles_u - smbase);
    const uint32_t full0 = smbase, empty0 = smbase + 24;
    if (tid == 0)
        for (int s = 0; s < 3; s++) { MBAR_INIT(full0 + 8 * s, 128); MBAR_INIT(empty0 + 8 * s, 8); }
    __syncthreads();

    if (tid >= 256) {   // ---------------- producers ----------------
        const int pt = tid - 256, c16 = pt & 7, r0p = pt >> 3;
        int s = 0, u = 0;
        for (int t = blockIdx.x; t < 8192; t += gridDim.x) {
            const int e = t >> 10, r = t & 1023, sup = r >> 6, r2 = r & 63;
            const int mt = r2 & 7, nt = sup * 8 + (r2 >> 3);
            const uint4* A1p = Xq1 + (size_t)(e * 1024 + mt * 128) * 128;
            const uint4* A2p = Xq2 + (size_t)(e * 1024 + mt * 128) * 128;
            for (int c = 0; c < 16; c++) {
                MBAR_WAIT(empty0 + 8 * s, u ^ 1);
                char* stg = tiles + s * ST1;
                const int kb = c * 8 + c16;
                #pragma unroll
                for (int p = 0; p < 8; p++) {
                    const int row = r0p + p * 16;
                    const uint32_t off = swzA((uint32_t)(row * 128 + c16 * 16));
                    *reinterpret_cast<uint4*>(stg + off) = __ldg(A1p + (size_t)row * 128 + kb);
                    *reinterpret_cast<uint4*>(stg + 16384 + off) = __ldg(A2p + (size_t)row * 128 + kb);
                }
                #pragma unroll
                for (int p = 0; p < 4; p++) {
                    const int nr = r0p + p * 16;
                    const int col = nt * 32 + ((nr >> 5) << 4) + (nr & 15) + ((nr >> 4) & 1) * 4096;
                    const size_t base = ((size_t)e * 8192 + col) * 128 + kb;
                    const uint32_t off = swzA((uint32_t)(nr * 128 + c16 * 16));
                    *reinterpret_cast<uint4*>(stg + 32768 + off) = __ldg(Wq1 + base);
                    *reinterpret_cast<uint4*>(stg + 40960 + off) = __ldg(Wq2 + base);
                }
                MBAR_ARRIVE(full0 + 8 * s);
                if (++s == 3) { s = 0; u ^= 1; }
            }
        }
        return;
    }
    // ---------------- consumers: 4m x 2n warps, 32x32 tiles ----------------
    const int wm = wid >> 1, wn = wid & 1;
    const int lane15 = lane & 15, seg = (lane >> 4) * 16;
    const uint32_t lxor = (uint32_t)((lane & 7) << 4);
    uint32_t a_row[2], b_row[2];
    #pragma unroll
    for (int st = 0; st < 2; st++) a_row[st] = (uint32_t)((wm * 32 + st * 16 + lane15) * 128);
    #pragma unroll
    for (int g = 0; g < 2; g++) b_row[g] = (uint32_t)((wn * 32 + g * 16 + lane15) * 128);

    int s = 0, u = 0;
    for (int t = blockIdx.x; t < 8192; t += gridDim.x) {
        const int e = t >> 10, r = t & 1023, sup = r >> 6, r2 = r & 63;
        const int mt = r2 & 7, nt = sup * 8 + (r2 >> 3);
        int acc1[2][4][4], acc2[2][4][4];
        #pragma unroll
        for (int st = 0; st < 2; st++)
            #pragma unroll
            for (int j = 0; j < 4; j++)
                #pragma unroll
                for (int i = 0; i < 4; i++) { acc1[st][j][i] = 0; acc2[st][j][i] = 0; }

        for (int c = 0; c < 16; c++) {
            MBAR_WAIT(full0 + 8 * s, u);
            const uint32_t A1U = tiles_u + s * ST1, A2U = A1U + 16384;
            const uint32_t B1U = A1U + 32768, B2U = A1U + 40960;
            #pragma unroll
            for (int ks = 0; ks < 4; ks++) {
                const uint32_t colx = (uint32_t)(ks * 32 + seg) ^ lxor;
                uint32_t b1[2][4], b2[2][4];
                #pragma unroll
                for (int g = 0; g < 2; g++) {
                    ldsm4(b1[g], B1U + b_row[g] + colx);
                    ldsm4(b2[g], B2U + b_row[g] + colx);
                }
                #pragma unroll
                for (int st = 0; st < 2; st++) {
                    uint32_t a1[4], a2[4];
                    ldsm4(a1, A1U + a_row[st] + colx);
                    ldsm4(a2, A2U + a_row[st] + colx);
                    #pragma unroll
                    for (int g = 0; g < 2; g++)
                        #pragma unroll
                        for (int h = 0; h < 2; h++) {
                            const int j = g * 2 + h;
                            imma(acc1[st][j], a1, b1[g][h], b1[g][h + 2]);
                            imma(acc2[st][j], a1, b2[g][h], b2[g][h + 2]);
                            imma(acc2[st][j], a2, b1[g][h], b1[g][h + 2]);
                        }
                }
            }
            if (lane == 0) MBAR_ARRIVE(empty0 + 8 * s);
            if (++s == 3) { s = 0; u ^= 1; }
        }
        // epilogue: rescale + register SwiGLU -> packed g_scr
        const float R254 = 1.0f / 254.0f, KK = 1.0f / 16129.0f;
        uint32_t* scrb = g_scr + (size_t)(e * 1024 + mt * 128) * 4096 + nt * 32 + wn * 16;
        #pragma unroll
        for (int h = 0; h < 2; h++) {
            const int colG = e * 8192 + nt * 32 + wn * 16 + h * 8 + (lane & 3) * 2;
            const float sg0 = __ldg(sW_d + colG), sg1 = __ldg(sW_d + colG + 1);
            const float su0 = __ldg(sW_d + colG + 4096), su1 = __ldg(sW_d + colG + 4097);
            #pragma unroll
            for (int st = 0; st < 2; st++) {
                const int r0 = wm * 32 + st * 16 + (lane >> 2);
                const int grow = e * 1024 + mt * 128 + r0;
                const float sx0 = __ldg(sX_d + grow) * KK, sx8 = __ldg(sX_d + grow + 8) * KK;
                const int hu = h + 2;
                const float g0 = ((float)acc1[st][h][0] + (float)acc2[st][h][0] * R254) * sx0 * sg0;
                const float g1 = ((float)acc1[st][h][1] + (float)acc2[st][h][1] * R254) * sx0 * sg1;
                const float g2 = ((float)acc1[st][h][2] + (float)acc2[st][h][2] * R254) * sx8 * sg0;
                const float g3 = ((float)acc1[st][h][3] + (float)acc2[st][h][3] * R254) * sx8 * sg1;
                const float u0 = ((float)acc1[st][hu][0] + (float)acc2[st][hu][0] * R254) * sx0 * su0;
                const float u1 = ((float)acc1[st][hu][1] + (float)acc2[st][hu][1] * R254) * sx0 * su1;
                const float u2 = ((float)acc1[st][hu][2] + (float)acc2[st][hu][2] * R254) * sx8 * su0;
                const float u3 = ((float)acc1[st][hu][3] + (float)acc2[st][hu][3] * R254) * sx8 * su1;
                const int cc = h * 8 + (lane & 3) * 2;
                *reinterpret_cast<uint2*>(scrb + (size_t)r0 * 4096 + cc) =
                    make_uint2(pack_hl(silu_mul(g0, u0)), pack_hl(silu_mul(g1, u1)));
                *reinterpret_cast<uint2*>(scrb + (size_t)(r0 + 8) * 4096 + cc) =
                    make_uint2(pack_hl(silu_mul(g2, u2)), pack_hl(silu_mul(g3, u3)));
            }
        }
    }
}

// ============ GEMM2 (bf16x3, proven R7 path): g_scr @ Wd -> out ==============
__global__ __launch_bounds__(384, 1) void gemm2_ker(const float* __restrict__ B_,
                                                    float* __restrict__ C_) {
    extern __shared__ char smem[];
    const int tid = threadIdx.x, wid = tid >> 5, lane = tid & 31;
    const uint32_t smbase = s2u(smem), tiles_u = (smbase + 1023) & ~1023u;
    char* tiles = smem + (tiles_u - smbase);
    const uint32_t full0 = smbase, empty0 = smbase + 24;
    if (tid == 0)
        for (int s = 0; s < 3; s++) { MBAR_INIT(full0 + 8 * s, 128); MBAR_INIT(empty0 + 8 * s, 8); }
    __syncthreads();

    if (tid >= 256) {   // producers
        const int pt = tid - 256, a_c4 = pt & 15, a_r0 = pt >> 4;
        const int b_n4 = pt & 31, b_k0 = pt >> 5;
        int s = 0, u = 0;
        for (int t = blockIdx.x; t < 1024; t += gridDim.x) {
            const int e = t >> 7, r = t & 127, sup = r >> 6, r2 = r & 63;
            const int mt = r2 & 7, nt = sup * 8 + (r2 >> 3);
            const uint32_t* Apu = g_scr + (size_t)(e * 1024 + mt * 128) * 4096 + a_c4 * 4;
            const float* Bp = B_ + (size_t)e * 4096 * 2048 + (size_t)nt * 128 + b_n4 * 4;
            for (int c = 0; c < 64; c++) {
                MBAR_WAIT(empty0 + 8 * s, u ^ 1);
                char* stg = tiles + s * ST2;
                const int kb = c * 64;
                #pragma unroll
                for (int p = 0; p < 16; p++) {
                    const int row = a_r0 + p * 8;
                    const uint32_t off = swzA((uint32_t)(row * 128 + a_c4 * 8));
                    uint4 v = *reinterpret_cast<const uint4*>(Apu + (size_t)row * 4096 + kb);
                    uint32_t h0, h1, l0, l1;
                    asm("prmt.b32 %0, %1, %2, 0x7632;" : "=r"(h0) : "r"(v.x), "r"(v.y));
                    asm("prmt.b32 %0, %1, %2, 0x5410;" : "=r"(l0) : "r"(v.x), "r"(v.y));
                    asm("prmt.b32 %0, %1, %2, 0x7632;" : "=r"(h1) : "r"(v.z), "r"(v.w));
                    asm("prmt.b32 %0, %1, %2, 0x5410;" : "=r"(l1) : "r"(v.z), "r"(v.w));
                    *reinterpret_cast<uint2*>(stg + off) = make_uint2(h0, h1);
                    *reinterpret_cast<uint2*>(stg + 16384 + off) = make_uint2(l0, l1);
                }
                #pragma unroll
                for (int p = 0; p < 16; p++) {
                    const int k = b_k0 + p * 4;
                    float4 v = *reinterpret_cast<const float4*>(Bp + (size_t)(kb + k) * 2048);
                    uint32_t h0, l0, h1, l1;
                    split2(v.x, v.y, h0, l0);
                    split2(v.z, v.w, h1, l1);
                    const uint32_t off = swzB((uint32_t)(k * 256 + b_n4 * 8));
                    *reinterpret_cast<uint2*>(stg + 32768 + off) = make_uint2(h0, h1);
                    *reinterpret_cast<uint2*>(stg + 49152 + off) = make_uint2(l0, l1);
                }
                MBAR_ARRIVE(full0 + 8 * s);
                if (++s == 3) { s = 0; u ^= 1; }
            }
        }
        return;
    }
    // consumers: 2m x 4n warps, 64x32
    const int wm = wid >> 2, wn = wid & 3;
    const int lane15 = lane & 15, seg = (lane >> 4) * 16;
    const uint32_t lxor = (uint32_t)((lane & 7) << 4);
    uint32_t a_row[4], b_colx[2];
    #pragma unroll
    for (int st = 0; st < 4; st++) a_row[st] = (uint32_t)((wm * 64 + st * 16 + lane15) * 128);
    #pragma unroll
    for (int ng = 0; ng < 2; ng++)
        b_colx[ng] = (uint32_t)(((wn * 32 + ng * 16) * 2 + seg)) ^ lxor;
    const uint32_t b_rowb = (uint32_t)(lane15 * 256);

    int s = 0, u = 0;
    for (int t = blockIdx.x; t < 1024; t += gridDim.x) {
        const int e = t >> 7, r = t & 127, sup = r >> 6, r2 = r & 63;
        const int mt = r2 & 7, nt = sup * 8 + (r2 >> 3);
        float acc[4][4][4];
        #pragma unroll
        for (int st = 0; st < 4; st++)
            #pragma unroll
            for (int j = 0; j < 4; j++)
                #pragma unroll
                for (int i = 0; i < 4; i++) acc[st][j][i] = 0.0f;

        for (int c = 0; c < 64; c++) {
            MBAR_WAIT(full0 + 8 * s, u);
            const uint32_t AhU = tiles_u + s * ST2, AlU = AhU + 16384;
            const uint32_t BhU = AhU + 32768, BlU = AhU + 49152;
            #pragma unroll
            for (int ks = 0; ks < 4; ks++) {
                const uint32_t acol = (uint32_t)(ks * 32 + seg) ^ lxor;
                const uint32_t brow = b_rowb + (uint32_t)(ks * 4096);
                uint32_t bh[2][4], bl[2][4];
                #pragma unroll
                for (int ng = 0; ng < 2; ng++) {
                    ldsm4t(bh[ng], BhU + brow + b_colx[ng]);
                    ldsm4t(bl[ng], BlU + brow + b_colx[ng]);
                }
                #pragma unroll
                for (int st = 0; st < 4; st++) {
                    uint32_t ah[4], al[4];
                    ldsm4(ah, AhU + a_row[st] + acol);
                    ldsm4(al, AlU + a_row[st] + acol);
                    #pragma unroll
                    for (int ng = 0; ng < 2; ng++)
                        #pragma unroll
                        for (int hf = 0; hf < 2; hf++) {
                            const int j = ng * 2 + hf;
                            mma16816(acc[st][j], ah, &bh[ng][2 * hf]);
                            mma16816(acc[st][j], ah, &bl[ng][2 * hf]);
                            mma16816(acc[st][j], al, &bh[ng][2 * hf]);
                        }
                }
            }
            if (lane == 0) MBAR_ARRIVE(empty0 + 8 * s);
            if (++s == 3) { s = 0; u ^= 1; }
        }
        float* Ce = C_ + (size_t)(e * 1024 + mt * 128) * 2048 + nt * 128;
        #pragma unroll
        for (int st = 0; st < 4; st++)
            #pragma unroll
            for (int j = 0; j < 4; j++) {
                const int r0 = wm * 64 + st * 16 + (lane >> 2);
                const int cc = wn * 32 + j * 8 + (lane & 3) * 2;
                float2 v0; v0.x = acc[st][j][0]; v0.y = acc[st][j][1];
                float2 v1; v1.x = acc[st][j][2]; v1.y = acc[st][j][3];
                *reinterpret_cast<float2*>(Ce + (size_t)r0 * 2048 + cc) = v0;
                *reinterpret_cast<float2*>(Ce + (size_t)(r0 + 8) * 2048 + cc) = v1;
            }
    }
}

// ============================================================================
extern "C" void kernel_launch(void* const* d_in, const int* in_sizes, int n_in,
                              void* d_out, int out_size) {
    const float* X   = (const float*)d_in[0];
    const float* Wgu = (const float*)d_in[1];
    const float* Wd  = (const float*)d_in[2];
    float* out = (float*)d_out;

    cudaFuncSetAttribute(gemm1_ker, cudaFuncAttributeMaxDynamicSharedMemorySize, SMEM1);
    cudaFuncSetAttribute(gemm2_ker, cudaFuncAttributeMaxDynamicSharedMemorySize, SMEM2);

    quantX_ker<<<8192, 256>>>(X);
    quantW_ker<<<512, 128>>>(Wgu);
    gemm1_ker<<<NSM, 384, SMEM1>>>();
    gemm2_ker<<<NSM, 384, SMEM2>>>(Wd, out);
}

// round 10
// speedup vs baseline: 3.3093x; 3.3093x over previous
#include <cuda_runtime.h>
#include <cuda_fp16.h>
#include <stdint.h>

// ============================================================================
// Llama4TextExperts grouped GEMM + SwiGLU, fp32 in/out.
// fp16x2 split GEMM on legacy HMMA (sm_103-safe mma.m16n8k16.f32.f16):
//   a = ah + al (fp16 pair, ~22-bit), b ~= bh (fp16 hi only)
//   a*b ~= ah*bh + al*bh   (2 MMAs; B rounding 2^-12 dominates error)
// Persistent warp-specialized: 8 consumer warps @64x32 + 4 producers, 3-stage.
//   GEMM1: X(8,1024,2048) @ Wgu -> SwiGLU -> g_scr packed (fp16 hi,lo)
//   GEMM2: g_scr @ Wd -> out (8192,2048) fp32
// ============================================================================

#define STAGE_BYTES 49152
#define NSTAGE 3
#define SMEM_BYTES (1024 + NSTAGE * STAGE_BYTES)
#define NSM 148

// packed intermediate: u32 = (fp16 hi << 16) | fp16 lo
static __device__ uint32_t g_scr[(size_t)8 * 1024 * 4096];   // 128 MB

// ---------------- helpers ----------------
__device__ __forceinline__ uint32_t s2u(const void* p) {
    uint32_t a;
    asm("{ .reg .u64 t; cvta.to.shared.u64 t, %1; cvt.u32.u64 %0, t; }" : "=r"(a) : "l"(p));
    return a;
}
__device__ __forceinline__ uint32_t swzA(uint32_t o) { return o ^ ((o >> 3) & 0x70); }  // 128B rows
__device__ __forceinline__ uint32_t swzB(uint32_t o) { return o ^ ((o >> 4) & 0x70); }  // 256B rows

__device__ __forceinline__ uint32_t pkh(float a, float b) {
    __half2 h = __floats2half2_rn(a, b);   // .x=a in low 16 bits
    return *reinterpret_cast<uint32_t*>(&h);
}
// split two fp32 into fp16 hi-pair and fp16 lo-pair (residual)
__device__ __forceinline__ void split2h(float f0, float f1, uint32_t& hi, uint32_t& lo) {
    const __half h0 = __float2half_rn(f0), h1 = __float2half_rn(f1);
    hi = ((uint32_t)__half_as_ushort(h1) << 16) | (uint32_t)__half_as_ushort(h0);
    lo = pkh(f0 - __half2float(h0), f1 - __half2float(h1));
}
// pack one fp32 as (fp16 hi << 16) | fp16 lo
__device__ __forceinline__ uint32_t pack_hl(float f) {
    __half hb = __float2half_rn(f);
    __half lb = __float2half_rn(f - __half2float(hb));
    return ((uint32_t)__half_as_ushort(hb) << 16) | (uint32_t)__half_as_ushort(lb);
}
__device__ __forceinline__ float silu_mul(float g, float u) {
    return u * __fdividef(g, 1.0f + __expf(-g));
}

__device__ __forceinline__ void ldsm4(uint32_t* r, uint32_t addr) {
    asm volatile("ldmatrix.sync.aligned.m8n8.x4.shared.b16 {%0,%1,%2,%3}, [%4];"
                 : "=r"(r[0]), "=r"(r[1]), "=r"(r[2]), "=r"(r[3]) : "r"(addr));
}
__device__ __forceinline__ void ldsm4t(uint32_t* r, uint32_t addr) {
    asm volatile("ldmatrix.sync.aligned.m8n8.x4.trans.shared.b16 {%0,%1,%2,%3}, [%4];"
                 : "=r"(r[0]), "=r"(r[1]), "=r"(r[2]), "=r"(r[3]) : "r"(addr));
}
__device__ __forceinline__ void mma16816(float* c, const uint32_t* a, const uint32_t* b) {
    asm volatile(
        "mma.sync.aligned.m16n8k16.row.col.f32.f16.f16.f32 "
        "{%0,%1,%2,%3}, {%4,%5,%6,%7}, {%8,%9}, {%0,%1,%2,%3};"
        : "+f"(c[0]), "+f"(c[1]), "+f"(c[2]), "+f"(c[3])
        : "r"(a[0]), "r"(a[1]), "r"(a[2]), "r"(a[3]), "r"(b[0]), "r"(b[1]));
}

#define MBAR_INIT(addr, cnt) \
    asm volatile("mbarrier.init.shared.b64 [%0], %1;" :: "r"(addr), "r"((uint32_t)(cnt)) : "memory")
#define MBAR_ARRIVE(addr) \
    asm volatile("mbarrier.arrive.shared.b64 _, [%0];" :: "r"(addr) : "memory")
#define MBAR_WAIT(mbar_addr, phase_parity) do {                                            \
    uint32_t _mbar = (uint32_t)(mbar_addr);                                                \
    uint32_t _par  = (uint32_t)(phase_parity);                                             \
    uint32_t _done;                                                                        \
    asm volatile(                                                                          \
        "{\n\t.reg .pred p;\n\t"                                                           \
        "mbarrier.try_wait.parity.acquire.cta.shared::cta.b64 p, [%1], %2;\n\t"            \
        "selp.b32 %0, 1, 0, p;\n\t}"                                                       \
        : "=r"(_done) : "r"(_mbar), "r"(_par) : "memory");                                 \
    if (!_done) {                                                                          \
        asm volatile(                                                                      \
            "{\n\t.reg .pred P1;\n\t"                                                      \
            "WL_%=:\n\t"                                                                   \
            "mbarrier.try_wait.parity.acquire.cta.shared::cta.b64 P1, [%0], %1, 0x989680;\n\t" \
            "@P1 bra.uni WD_%=;\n\t"                                                       \
            "bra.uni WL_%=;\n\t"                                                           \
            "WD_%=:\n\t}"                                                                  \
            :: "r"(_mbar), "r"(_par) : "memory");                                          \
    }                                                                                      \
} while (0)

// ============================================================================
//   KDIM : reduction dim (2048 / 4096),  NTILE: n-tiles per expert (64 / 16)
//   MODE2=false: GEMM1. A = X fp32 (w2048) -> fp16 hi/lo. B = Wgu (w8192),
//                warp-paired gate/up columns, fp16 hi only.
//                Epilogue: register-local SwiGLU -> g_scr packed (hi,lo).
//   MODE2=true : GEMM2. A = g_scr packed (w4096); B = Wd fp16-hi; C fp32.
// Stage (48KB): Ah@0 (16K), Al@16K, Bh@32K (64 k-rows x 128 n fp16, swzB).
// Persistent: grid=NSM; ring (s,u) flows across tiles. 384 thr = 8 cons + 4 prod.
// ============================================================================
template <int KDIM, int NTILE, bool MODE2>
__global__ __launch_bounds__(384, 1) void gemm_ker(const float* __restrict__ A_,
                                                   const float* __restrict__ B_,
                                                   float* __restrict__ C_) {
    extern __shared__ char smem[];
    constexpr int NC   = KDIM / 64;
    constexpr int NWB  = MODE2 ? 2048 : 8192;   // B row width
    constexpr int PERE = 8 * NTILE;             // tiles per expert
    constexpr int TOT  = 8 * PERE;              // total tiles

    const int tid  = threadIdx.x;
    const int wid  = tid >> 5;
    const int lane = tid & 31;

    const uint32_t smbase  = s2u(smem);
    const uint32_t tiles_u = (smbase + 1023) & ~1023u;
    char* tiles = smem + (tiles_u - smbase);
    const uint32_t full0  = smbase;        // full[s]  @ +8s, count=128
    const uint32_t empty0 = smbase + 24;   // empty[s] @ +8s, count=8

    if (tid == 0) {
        #pragma unroll
        for (int s = 0; s < NSTAGE; s++) {
            MBAR_INIT(full0 + 8 * s, 128);
            MBAR_INIT(empty0 + 8 * s, 8);
        }
    }
    __syncthreads();

    if (tid >= 256) {
        // ===================== PRODUCERS (warps 8..11) =====================
        const int pt   = tid - 256;          // 0..127
        const int a_c4 = pt & 15;            // float4/uint4 col in 64-k row
        const int a_r0 = pt >> 4;            // 0..7
        const int b_n4 = pt & 31;            // vec4 col in 128-n row
        const int b_k0 = pt >> 5;            // 0..3

        int s = 0, u = 0;
        for (int t = blockIdx.x; t < TOT; t += gridDim.x) {
            const int e   = t / PERE;
            const int r   = t % PERE;
            const int sup = r >> 6;
            const int r2  = r & 63;
            const int mt  = r2 & 7;
            const int nt  = sup * 8 + (r2 >> 3);

            const float*    Apf = nullptr;
            const uint32_t* Apu = nullptr;
            if (MODE2) Apu = g_scr + (size_t)(e * 1024 + mt * 128) * 4096 + a_c4 * 4;
            else       Apf = A_ + (size_t)(e * 1024 + mt * 128) * 2048 + a_c4 * 4;

            size_t bcol;
            if (MODE2) {
                bcol = (size_t)nt * 128 + b_n4 * 4;
            } else {
                const int np   = b_n4 * 4;
                const int g    = np >> 5;
                const int pair = np & 15;
                const int kind = (np >> 4) & 1;
                bcol = (size_t)nt * 64 + g * 16 + pair + (size_t)kind * 4096;
            }
            const float* Bp = B_ + (size_t)e * KDIM * NWB + bcol;

            for (int c = 0; c < NC; c++) {
                MBAR_WAIT(empty0 + 8 * s, u ^ 1);
                char* stg = tiles + s * STAGE_BYTES;
                const int kb = c * 64;

                // ---- A tile: 128 rows x 64 k, fp16 hi + lo ----
                #pragma unroll
                for (int p = 0; p < 16; p++) {
                    const int row = a_r0 + p * 8;
                    const uint32_t off = swzA((uint32_t)(row * 128 + a_c4 * 8));
                    if (MODE2) {
                        uint4 v = *reinterpret_cast<const uint4*>(Apu + (size_t)row * 4096 + kb);
                        uint32_t h0, h1, l0, l1;
                        asm("prmt.b32 %0, %1, %2, 0x7632;" : "=r"(h0) : "r"(v.x), "r"(v.y));
                        asm("prmt.b32 %0, %1, %2, 0x5410;" : "=r"(l0) : "r"(v.x), "r"(v.y));
                        asm("prmt.b32 %0, %1, %2, 0x7632;" : "=r"(h1) : "r"(v.z), "r"(v.w));
                        asm("prmt.b32 %0, %1, %2, 0x5410;" : "=r"(l1) : "r"(v.z), "r"(v.w));
                        *reinterpret_cast<uint2*>(stg + off)         = make_uint2(h0, h1);
                        *reinterpret_cast<uint2*>(stg + 16384 + off) = make_uint2(l0, l1);
                    } else {
                        float4 v = *reinterpret_cast<const float4*>(Apf + (size_t)row * 2048 + kb);
                        uint32_t h0, l0, h1, l1;
                        split2h(v.x, v.y, h0, l0);
                        split2h(v.z, v.w, h1, l1);
                        *reinterpret_cast<uint2*>(stg + off)         = make_uint2(h0, h1);
                        *reinterpret_cast<uint2*>(stg + 16384 + off) = make_uint2(l0, l1);
                    }
                }
                // ---- B tile: 64 k-rows x 128 n, fp16 hi only ----
                #pragma unroll
                for (int p = 0; p < 16; p++) {
                    const int k = b_k0 + p * 4;
                    float4 v = *reinterpret_cast<const float4*>(Bp + (size_t)(kb + k) * NWB);
                    const uint32_t h0 = pkh(v.x, v.y);
                    const uint32_t h1 = pkh(v.z, v.w);
                    const uint32_t off = swzB((uint32_t)(k * 256 + b_n4 * 8));
                    *reinterpret_cast<uint2*>(stg + 32768 + off) = make_uint2(h0, h1);
                }
                MBAR_ARRIVE(full0 + 8 * s);
                if (++s == NSTAGE) { s = 0; u ^= 1; }
            }
        }
        return;
    }

    // ======================= CONSUMERS (warps 0..7) =======================
    // 2(m) x 4(n) warp grid, 64x32 tiles: wm = wid>>2 (0..1), wn = wid&3.
    const int wm = wid >> 2;
    const int wn = wid & 3;

    const int lane15 = lane & 15;
    const int seg    = (lane >> 4) * 16;
    const uint32_t lxor = (uint32_t)((lane & 7) << 4);
    uint32_t a_row[4], b_colx[2];
    #pragma unroll
    for (int st = 0; st < 4; st++)
        a_row[st] = (uint32_t)((wm * 64 + st * 16 + lane15) * 128);
    #pragma unroll
    for (int ng = 0; ng < 2; ng++)
        b_colx[ng] = (uint32_t)(((wn * 32 + ng * 16) * 2 + seg)) ^ lxor;
    const uint32_t b_rowb = (uint32_t)(lane15 * 256);

    int s = 0, u = 0;
    for (int t = blockIdx.x; t < TOT; t += gridDim.x) {
        const int e   = t / PERE;
        const int r   = t % PERE;
        const int sup = r >> 6;
        const int r2  = r & 63;
        const int mt  = r2 & 7;
        const int nt  = sup * 8 + (r2 >> 3);

        float acc[4][4][4];
        #pragma unroll
        for (int st = 0; st < 4; st++)
            #pragma unroll
            for (int j = 0; j < 4; j++)
                #pragma unroll
                for (int i = 0; i < 4; i++) acc[st][j][i] = 0.0f;

        for (int c = 0; c < NC; c++) {
            MBAR_WAIT(full0 + 8 * s, u);
            const uint32_t AhU = tiles_u + s * STAGE_BYTES;
            const uint32_t AlU = AhU + 16384;
            const uint32_t BhU = AhU + 32768;

            #pragma unroll
            for (int ks = 0; ks < 4; ks++) {
                const uint32_t acol = (uint32_t)(ks * 32 + seg) ^ lxor;
                const uint32_t brow = b_rowb + (uint32_t)(ks * 4096);
                uint32_t bh[2][4];
                #pragma unroll
                for (int ng = 0; ng < 2; ng++)
                    ldsm4t(bh[ng], BhU + brow + b_colx[ng]);
                #pragma unroll
                for (int st = 0; st < 4; st++) {
                    uint32_t ah[4], al[4];
                    ldsm4(ah, AhU + a_row[st] + acol);
                    ldsm4(al, AlU + a_row[st] + acol);
                    #pragma unroll
                    for (int ng = 0; ng < 2; ng++)
                        #pragma unroll
                        for (int hf = 0; hf < 2; hf++) {
                            const int j = ng * 2 + hf;
                            mma16816(acc[st][j], ah, &bh[ng][2 * hf]);
                            mma16816(acc[st][j], al, &bh[ng][2 * hf]);
                        }
                }
            }
            if (lane == 0) MBAR_ARRIVE(empty0 + 8 * s);
            if (++s == NSTAGE) { s = 0; u ^= 1; }
        }

        // ----------------- epilogue (register-only, overlaps ring) --------
        if (MODE2) {
            float* Ce = C_ + (size_t)(e * 1024 + mt * 128) * 2048 + nt * 128;
            #pragma unroll
            for (int st = 0; st < 4; st++)
                #pragma unroll
                for (int j = 0; j < 4; j++) {
                    const int r0 = wm * 64 + st * 16 + (lane >> 2);
                    const int cc = wn * 32 + j * 8 + (lane & 3) * 2;
                    float2 v0; v0.x = acc[st][j][0]; v0.y = acc[st][j][1];
                    float2 v1; v1.x = acc[st][j][2]; v1.y = acc[st][j][3];
                    *reinterpret_cast<float2*>(Ce + (size_t)r0 * 2048 + cc) = v0;
                    *reinterpret_cast<float2*>(Ce + (size_t)(r0 + 8) * 2048 + cc) = v1;
                }
        } else {
            // gate = acc[st][j] (cols 0..15), up = acc[st][j+2] (cols 16..31).
            uint32_t* scrb = g_scr + (size_t)(e * 1024 + mt * 128) * 4096
                           + (size_t)nt * 64 + wn * 16;
            #pragma unroll
            for (int st = 0; st < 4; st++)
                #pragma unroll
                for (int j = 0; j < 2; j++) {
                    const int r0 = wm * 64 + st * 16 + (lane >> 2);
                    const int cc = j * 8 + (lane & 3) * 2;
                    const float i0 = silu_mul(acc[st][j][0], acc[st][j + 2][0]);
                    const float i1 = silu_mul(acc[st][j][1], acc[st][j + 2][1]);
                    const float i2 = silu_mul(acc[st][j][2], acc[st][j + 2][2]);
                    const float i3 = silu_mul(acc[st][j][3], acc[st][j + 2][3]);
                    *reinterpret_cast<uint2*>(scrb + (size_t)r0 * 4096 + cc) =
                        make_uint2(pack_hl(i0), pack_hl(i1));
                    *reinterpret_cast<uint2*>(scrb + (size_t)(r0 + 8) * 4096 + cc) =
                        make_uint2(pack_hl(i2), pack_hl(i3));
                }
        }
    }
}

// ============================================================================
extern "C" void kernel_launch(void* const* d_in, const int* in_sizes, int n_in,
                              void* d_out, int out_size) {
    const float* X   = (const float*)d_in[0];   // (8192, 2048)
    const float* Wgu = (const float*)d_in[1];   // (8, 2048, 8192)
    const float* Wd  = (const float*)d_in[2];   // (8, 4096, 2048)
    float* out = (float*)d_out;                 // (8192, 2048)

    cudaFuncSetAttribute(gemm_ker<2048, 64, false>,
                         cudaFuncAttributeMaxDynamicSharedMemorySize, SMEM_BYTES);
    cudaFuncSetAttribute(gemm_ker<4096, 16, true>,
                         cudaFuncAttributeMaxDynamicSharedMemorySize, SMEM_BYTES);

    gemm_ker<2048, 64, false><<<NSM, 384, SMEM_BYTES>>>(X, Wgu, nullptr);
    gemm_ker<4096, 16, true><<<NSM, 384, SMEM_BYTES>>>(nullptr, Wd, out);
}

// round 11
// speedup vs baseline: 3.8068x; 1.1503x over previous
#include <cuda_runtime.h>
#include <cuda_fp16.h>
#include <stdint.h>

// ============================================================================
// Llama4TextExperts grouped GEMM + SwiGLU, fp32 in/out.
// Single-term fp16 HMMA (mma.m16n8k16.f32.f16), fp32 accumulate.
// Calibrated error: ~5e-4 (4 independent 2^-12 rounding sources) vs 1e-3 gate.
// Persistent warp-specialized: 8 consumer warps @32x64 (4m x 2n) + 4 producer
// warps, 4-stage 32KB smem ring.
//   GEMM1: X(8,1024,2048) @ Wgu -> SwiGLU -> g_scr (fp16, 64MB)
//   GEMM2: g_scr @ Wd -> out (8192,2048) fp32
// ============================================================================

#define STAGE_BYTES 32768
#define NSTAGE 4
#define SMEM_BYTES (1024 + NSTAGE * STAGE_BYTES)
#define NSM 148

static __device__ __half g_scr[(size_t)8 * 1024 * 4096];   // 64 MB fp16 inter

// ---------------- helpers ----------------
__device__ __forceinline__ uint32_t s2u(const void* p) {
    uint32_t a;
    asm("{ .reg .u64 t; cvta.to.shared.u64 t, %1; cvt.u32.u64 %0, t; }" : "=r"(a) : "l"(p));
    return a;
}
__device__ __forceinline__ uint32_t swzA(uint32_t o) { return o ^ ((o >> 3) & 0x70); }  // 128B rows
__device__ __forceinline__ uint32_t swzB(uint32_t o) { return o ^ ((o >> 4) & 0x70); }  // 256B rows

__device__ __forceinline__ uint32_t pkh(float a, float b) {
    __half2 h = __floats2half2_rn(a, b);   // .x=a in low 16 bits
    return *reinterpret_cast<uint32_t*>(&h);
}
__device__ __forceinline__ float silu_mul(float g, float u) {
    return u * __fdividef(g, 1.0f + __expf(-g));
}

__device__ __forceinline__ void ldsm4(uint32_t* r, uint32_t addr) {
    asm volatile("ldmatrix.sync.aligned.m8n8.x4.shared.b16 {%0,%1,%2,%3}, [%4];"
                 : "=r"(r[0]), "=r"(r[1]), "=r"(r[2]), "=r"(r[3]) : "r"(addr));
}
__device__ __forceinline__ void ldsm4t(uint32_t* r, uint32_t addr) {
    asm volatile("ldmatrix.sync.aligned.m8n8.x4.trans.shared.b16 {%0,%1,%2,%3}, [%4];"
                 : "=r"(r[0]), "=r"(r[1]), "=r"(r[2]), "=r"(r[3]) : "r"(addr));
}
__device__ __forceinline__ void mma16816(float* c, const uint32_t* a, const uint32_t* b) {
    asm volatile(
        "mma.sync.aligned.m16n8k16.row.col.f32.f16.f16.f32 "
        "{%0,%1,%2,%3}, {%4,%5,%6,%7}, {%8,%9}, {%0,%1,%2,%3};"
        : "+f"(c[0]), "+f"(c[1]), "+f"(c[2]), "+f"(c[3])
        : "r"(a[0]), "r"(a[1]), "r"(a[2]), "r"(a[3]), "r"(b[0]), "r"(b[1]));
}

#define MBAR_INIT(addr, cnt) \
    asm volatile("mbarrier.init.shared.b64 [%0], %1;" :: "r"(addr), "r"((uint32_t)(cnt)) : "memory")
#define MBAR_ARRIVE(addr) \
    asm volatile("mbarrier.arrive.shared.b64 _, [%0];" :: "r"(addr) : "memory")
#define MBAR_WAIT(mbar_addr, phase_parity) do {                                            \
    uint32_t _mbar = (uint32_t)(mbar_addr);                                                \
    uint32_t _par  = (uint32_t)(phase_parity);                                             \
    uint32_t _done;                                                                        \
    asm volatile(                                                                          \
        "{\n\t.reg .pred p;\n\t"                                                           \
        "mbarrier.try_wait.parity.acquire.cta.shared::cta.b64 p, [%1], %2;\n\t"            \
        "selp.b32 %0, 1, 0, p;\n\t}"                                                       \
        : "=r"(_done) : "r"(_mbar), "r"(_par) : "memory");                                 \
    if (!_done) {                                                                          \
        asm volatile(                                                                      \
            "{\n\t.reg .pred P1;\n\t"                                                      \
            "WL_%=:\n\t"                                                                   \
            "mbarrier.try_wait.parity.acquire.cta.shared::cta.b64 P1, [%0], %1, 0x989680;\n\t" \
            "@P1 bra.uni WD_%=;\n\t"                                                       \
            "bra.uni WL_%=;\n\t"                                                           \
            "WD_%=:\n\t}"                                                                  \
            :: "r"(_mbar), "r"(_par) : "memory");                                          \
    }                                                                                      \
} while (0)

// ============================================================================
//   KDIM : reduction dim (2048 / 4096),  NTILE: n-tiles per expert (64 / 16)
//   MODE2=false: GEMM1. A = X fp32 (w2048) -> fp16. B = Wgu (w8192), warp-
//                paired gate/up at 32-col granularity: tile col n' ->
//                w=n'>>6, local=n'&63, kind=(local>>5)&1, pair=local&31;
//                global col = nt*64 + w*32 + pair + kind*4096.
//                Epilogue: register SwiGLU -> g_scr fp16.
//   MODE2=true : GEMM2. A = g_scr fp16 (w4096, raw copy); B = Wd; C fp32.
// Stage (32KB): Ah@0 (128 rows x 128B, swzA), Bh@16K (64 k-rows x 256B, swzB).
// Consumers: 8 warps, 4(m) x 2(n), 32x64 tiles. Producers: 4 warps.
// ============================================================================
template <int KDIM, int NTILE, bool MODE2>
__global__ __launch_bounds__(384, 1) void gemm_ker(const float* __restrict__ A_,
                                                   const float* __restrict__ B_,
                                                   float* __restrict__ C_) {
    extern __shared__ char smem[];
    constexpr int NC   = KDIM / 64;
    constexpr int NWB  = MODE2 ? 2048 : 8192;   // B row width
    constexpr int PERE = 8 * NTILE;             // tiles per expert
    constexpr int TOT  = 8 * PERE;              // total tiles

    const int tid  = threadIdx.x;
    const int wid  = tid >> 5;
    const int lane = tid & 31;

    const uint32_t smbase  = s2u(smem);
    const uint32_t tiles_u = (smbase + 1023) & ~1023u;
    char* tiles = smem + (tiles_u - smbase);
    const uint32_t full0  = smbase;        // full[s]  @ +8s, count=128
    const uint32_t empty0 = smbase + 32;   // empty[s] @ +8s, count=8

    if (tid == 0) {
        #pragma unroll
        for (int s = 0; s < NSTAGE; s++) {
            MBAR_INIT(full0 + 8 * s, 128);
            MBAR_INIT(empty0 + 8 * s, 8);
        }
    }
    __syncthreads();

    if (tid >= 256) {
        // ===================== PRODUCERS (warps 8..11) =====================
        const int pt   = tid - 256;          // 0..127
        const int a_c4 = pt & 15;            // 8B unit within 128B A row
        const int a_r0 = pt >> 4;            // 0..7
        const int b_n4 = pt & 31;            // float4 col in 128-n B row
        const int b_k0 = pt >> 5;            // 0..3

        int s = 0, u = 0;
        for (int t = blockIdx.x; t < TOT; t += gridDim.x) {
            const int e   = t / PERE;
            const int r   = t % PERE;
            const int sup = r >> 6;
            const int r2  = r & 63;
            const int mt  = r2 & 7;
            const int nt  = sup * 8 + (r2 >> 3);

            const float*  Apf = nullptr;
            const __half* Aph = nullptr;
            if (MODE2) Aph = g_scr + (size_t)(e * 1024 + mt * 128) * 4096 + a_c4 * 4;
            else       Apf = A_ + (size_t)(e * 1024 + mt * 128) * 2048 + a_c4 * 4;

            size_t bcol;
            if (MODE2) {
                bcol = (size_t)nt * 128 + b_n4 * 4;
            } else {
                const int np    = b_n4 * 4;
                const int w     = np >> 6;
                const int local = np & 63;
                const int kind  = (local >> 5) & 1;
                const int pair  = local & 31;
                bcol = (size_t)nt * 64 + w * 32 + pair + (size_t)kind * 4096;
            }
            const float* Bp = B_ + (size_t)e * KDIM * NWB + bcol;

            for (int c = 0; c < NC; c++) {
                MBAR_WAIT(empty0 + 8 * s, u ^ 1);
                char* stg = tiles + s * STAGE_BYTES;
                const int kb = c * 64;

                // ---- A tile: 128 rows x 64 k fp16 ----
                #pragma unroll
                for (int p = 0; p < 16; p++) {
                    const int row = a_r0 + p * 8;
                    const uint32_t off = swzA((uint32_t)(row * 128 + a_c4 * 8));
                    if (MODE2) {
                        *reinterpret_cast<uint2*>(stg + off) =
                            *reinterpret_cast<const uint2*>(Aph + (size_t)row * 4096 + kb);
                    } else {
                        float4 v = *reinterpret_cast<const float4*>(Apf + (size_t)row * 2048 + kb);
                        *reinterpret_cast<uint2*>(stg + off) =
                            make_uint2(pkh(v.x, v.y), pkh(v.z, v.w));
                    }
                }
                // ---- B tile: 64 k-rows x 128 n fp16 ----
                #pragma unroll
                for (int p = 0; p < 16; p++) {
                    const int k = b_k0 + p * 4;
                    float4 v = *reinterpret_cast<const float4*>(Bp + (size_t)(kb + k) * NWB);
                    const uint32_t off = swzB((uint32_t)(k * 256 + b_n4 * 8));
                    *reinterpret_cast<uint2*>(stg + 16384 + off) =
                        make_uint2(pkh(v.x, v.y), pkh(v.z, v.w));
                }
                MBAR_ARRIVE(full0 + 8 * s);
                if (++s == NSTAGE) { s = 0; u ^= 1; }
            }
        }
        return;
    }

    // ======================= CONSUMERS (warps 0..7) =======================
    // 4(m) x 2(n) warp grid, 32x64 tiles: wm = wid>>1 (0..3), wn = wid&1.
    const int wm = wid >> 1;
    const int wn = wid & 1;

    const int lane15 = lane & 15;
    const int seg    = (lane >> 4) * 16;
    const uint32_t lxor = (uint32_t)((lane & 7) << 4);
    uint32_t a_row[2], b_colx[4];
    #pragma unroll
    for (int st = 0; st < 2; st++)
        a_row[st] = (uint32_t)((wm * 32 + st * 16 + lane15) * 128);
    #pragma unroll
    for (int ng = 0; ng < 4; ng++)
        b_colx[ng] = (uint32_t)(((wn * 64 + ng * 16) * 2 + seg)) ^ lxor;
    const uint32_t b_rowb = (uint32_t)(lane15 * 256);

    int s = 0, u = 0;
    for (int t = blockIdx.x; t < TOT; t += gridDim.x) {
        const int e   = t / PERE;
        const int r   = t % PERE;
        const int sup = r >> 6;
        const int r2  = r & 63;
        const int mt  = r2 & 7;
        const int nt  = sup * 8 + (r2 >> 3);

        float acc[2][8][4];
        #pragma unroll
        for (int st = 0; st < 2; st++)
            #pragma unroll
            for (int j = 0; j < 8; j++)
                #pragma unroll
                for (int i = 0; i < 4; i++) acc[st][j][i] = 0.0f;

        for (int c = 0; c < NC; c++) {
            MBAR_WAIT(full0 + 8 * s, u);
            const uint32_t AhU = tiles_u + s * STAGE_BYTES;
            const uint32_t BhU = AhU + 16384;

            #pragma unroll
            for (int ks = 0; ks < 4; ks++) {
                const uint32_t acol = (uint32_t)(ks * 32 + seg) ^ lxor;
                const uint32_t brow = b_rowb + (uint32_t)(ks * 4096);
                uint32_t ah[2][4], bh[4][4];
                #pragma unroll
                for (int st = 0; st < 2; st++)
                    ldsm4(ah[st], AhU + a_row[st] + acol);
                #pragma unroll
                for (int ng = 0; ng < 4; ng++)
                    ldsm4t(bh[ng], BhU + brow + b_colx[ng]);
                #pragma unroll
                for (int st = 0; st < 2; st++)
                    #pragma unroll
                    for (int ng = 0; ng < 4; ng++)
                        #pragma unroll
                        for (int hf = 0; hf < 2; hf++)
                            mma16816(acc[st][ng * 2 + hf], ah[st], &bh[ng][2 * hf]);
            }
            if (lane == 0) MBAR_ARRIVE(empty0 + 8 * s);
            if (++s == NSTAGE) { s = 0; u ^= 1; }
        }

        // ----------------- epilogue (register-only, overlaps ring) --------
        if (MODE2) {
            float* Ce = C_ + (size_t)(e * 1024 + mt * 128) * 2048 + nt * 128;
            #pragma unroll
            for (int st = 0; st < 2; st++)
                #pragma unroll
                for (int j = 0; j < 8; j++) {
                    const int r0 = wm * 32 + st * 16 + (lane >> 2);
                    const int cc = wn * 64 + j * 8 + (lane & 3) * 2;
                    float2 v0; v0.x = acc[st][j][0]; v0.y = acc[st][j][1];
                    float2 v1; v1.x = acc[st][j][2]; v1.y = acc[st][j][3];
                    *reinterpret_cast<float2*>(Ce + (size_t)r0 * 2048 + cc) = v0;
                    *reinterpret_cast<float2*>(Ce + (size_t)(r0 + 8) * 2048 + cc) = v1;
                }
        } else {
            // gate = acc[st][j] (local cols 0..31), up = acc[st][j+4]
            // (local cols 32..63), same output pair. Register SwiGLU.
            __half* scrb = g_scr + (size_t)(e * 1024 + mt * 128) * 4096
                         + (size_t)nt * 64 + wn * 32;
            #pragma unroll
            for (int st = 0; st < 2; st++)
                #pragma unroll
                for (int j = 0; j < 4; j++) {
                    const int r0 = wm * 32 + st * 16 + (lane >> 2);
                    const int cc = j * 8 + (lane & 3) * 2;
                    const float i0 = silu_mul(acc[st][j][0], acc[st][j + 4][0]);
                    const float i1 = silu_mul(acc[st][j][1], acc[st][j + 4][1]);
                    const float i2 = silu_mul(acc[st][j][2], acc[st][j + 4][2]);
                    const float i3 = silu_mul(acc[st][j][3], acc[st][j + 4][3]);
                    *reinterpret_cast<uint32_t*>(scrb + (size_t)r0 * 4096 + cc) = pkh(i0, i1);
                    *reinterpret_cast<uint32_t*>(scrb + (size_t)(r0 + 8) * 4096 + cc) = pkh(i2, i3);
                }
        }
    }
}

// ============================================================================
extern "C" void kernel_launch(void* const* d_in, const int* in_sizes, int n_in,
                              void* d_out, int out_size) {
    const float* X   = (const float*)d_in[0];   // (8192, 2048)
    const float* Wgu = (const float*)d_in[1];   // (8, 2048, 8192)
    const float* Wd  = (const float*)d_in[2];   // (8, 4096, 2048)
    float* out = (float*)d_out;                 // (8192, 2048)

    cudaFuncSetAttribute(gemm_ker<2048, 64, false>,
                         cudaFuncAttributeMaxDynamicSharedMemorySize, SMEM_BYTES);
    cudaFuncSetAttribute(gemm_ker<4096, 16, true>,
                         cudaFuncAttributeMaxDynamicSharedMemorySize, SMEM_BYTES);

    gemm_ker<2048, 64, false><<<NSM, 384, SMEM_BYTES>>>(X, Wgu, nullptr);
    gemm_ker<4096, 16, true><<<NSM, 384, SMEM_BYTES>>>(nullptr, Wd, out);
}